// round 3
// baseline (speedup 1.0000x reference)
#include <cuda_runtime.h>
#include <math.h>

#define BB 64
#define TT 512
#define DIN 64
#define HH 512
#define G4 2048
#define DOUT 32

// ---------------- scratch (__device__ globals; no runtime allocation) --------
__device__ __align__(256) float g_xg[BB * TT * G4];   // gate pre-activations
__device__ __align__(256) float g_h1[BB * TT * HH];   // layer-0 output sequence
__device__ __align__(256) float g_gh[2][BB * HH];     // ping-pong hidden state
__device__ __align__(256) float g_hlast[BB * HH];     // layer-1 final h
__device__ unsigned g_bar;

typedef unsigned long long u64;

// ---------------- f32x2 helpers (Blackwell packed fp32 pipe) ------------------
__device__ __forceinline__ void fma2(u64& d, u64 a, u64 b) {
    asm("fma.rn.f32x2 %0, %1, %2, %0;" : "+l"(d) : "l"(a), "l"(b));
}
__device__ __forceinline__ float2 upk2(u64 v) {
    float lo, hi;
    asm("mov.b64 {%0, %1}, %2;" : "=f"(lo), "=f"(hi) : "l"(v));
    return make_float2(lo, hi);
}
__device__ __forceinline__ float sigm(float x) { return 1.0f / (1.0f + expf(-x)); }

// ---------------- C[M][N] = A[M][K] * B[N][K]^T + b1[n] + b2[n] ---------------
// BM=BN=64, BK=16, 256 threads, 4x4 thread tile, f32x2 dual-lane accumulation.
__global__ void __launch_bounds__(256) gemm_abT(
    float* __restrict__ C, const float* __restrict__ A, const float* __restrict__ Bm,
    const float* __restrict__ bias1, const float* __restrict__ bias2,
    int M, int N, int K)
{
    __shared__ __align__(16) float As[8 * 136];  // [k_pair][m*2 + parity]
    __shared__ __align__(16) float Bs[8 * 136];

    int tid = threadIdx.x;
    int bm = blockIdx.y, bn = blockIdx.x;
    int tx = tid & 15, ty = tid >> 4;

    u64 acc[4][4];
#pragma unroll
    for (int i = 0; i < 4; i++)
#pragma unroll
        for (int j = 0; j < 4; j++) acc[i][j] = 0ull;

    int r  = tid >> 2;         // 0..63 row within tile
    int kq = (tid & 3) * 4;    // 0,4,8,12
    const float* Ag = A + (size_t)(bm * 64 + r) * K + kq;
    const float* Bg = Bm + (size_t)(bn * 64 + r) * K + kq;

    for (int kt = 0; kt < K; kt += 16) {
        float4 av = *(const float4*)(Ag + kt);
        float4 bv = *(const float4*)(Bg + kt);
        __syncthreads();
        int s0 = (kq >> 1) * 136 + r * 2;
        *(float2*)(As + s0)       = make_float2(av.x, av.y);
        *(float2*)(As + s0 + 136) = make_float2(av.z, av.w);
        *(float2*)(Bs + s0)       = make_float2(bv.x, bv.y);
        *(float2*)(Bs + s0 + 136) = make_float2(bv.z, bv.w);
        __syncthreads();
#pragma unroll
        for (int kk = 0; kk < 8; kk++) {
            const ulonglong2* ap = (const ulonglong2*)(As + kk * 136 + ty * 8);
            const ulonglong2* bp = (const ulonglong2*)(Bs + kk * 136 + tx * 8);
            ulonglong2 a01 = ap[0], a23 = ap[1];
            ulonglong2 b01 = bp[0], b23 = bp[1];
            u64 af[4] = {a01.x, a01.y, a23.x, a23.y};
            u64 bf[4] = {b01.x, b01.y, b23.x, b23.y};
#pragma unroll
            for (int i = 0; i < 4; i++)
#pragma unroll
                for (int j = 0; j < 4; j++) fma2(acc[i][j], af[i], bf[j]);
        }
    }

#pragma unroll
    for (int i = 0; i < 4; i++) {
        int row = bm * 64 + ty * 4 + i;
        float4 o;
        float* ov = &o.x;
#pragma unroll
        for (int j = 0; j < 4; j++) {
            int coln = bn * 64 + tx * 4 + j;
            float2 s = upk2(acc[i][j]);
            ov[j] = s.x + s.y + bias1[coln] + bias2[coln];
        }
        *(float4*)(C + (size_t)row * N + bn * 64 + tx * 4) = o;
    }
}

// ---------------- persistent LSTM recurrence ---------------------------------
// grid = 128 co-resident CTAs, 256 threads. CTA owns h cols [4c,4c+4).
// thread: b = tid&63, jj = tid>>6; computes all 4 gates for (b, col).
#define SM_H  (64 * 514)      // staged h, row stride 514 (odd u64 stride)
#define SM_W  (16 * 520)      // 16 W_hh rows, stride 520 (16B-aligned)
#define SMEM_REC_BYTES ((SM_H + SM_W) * 4)

__global__ void __launch_bounds__(256, 1) lstm_rec(
    const float* __restrict__ Whh,   // [2048,512]
    const float* __restrict__ xg,    // [B,T,2048] = x-proj + b_ih + b_hh
    float* __restrict__ hseq,        // [B,T,512] or nullptr
    float* __restrict__ hlast)       // [B,512]   or nullptr
{
    extern __shared__ float sm[];
    float* h_s = sm;
    float* w_s = sm + SM_H;

    int tid = threadIdx.x;
    int b   = tid & 63;
    int jj  = tid >> 6;
    int col = blockIdx.x * 4 + jj;

    for (int i = tid; i < 16 * 512; i += 256) {
        int row = i >> 9, k = i & 511;
        int g = row >> 2, j2 = row & 3;
        w_s[row * 520 + k] = Whh[(size_t)(g * 512 + blockIdx.x * 4 + j2) * 512 + k];
    }
    float c = 0.0f;
    __syncthreads();

    const float* w0 = w_s + (0 * 4 + jj) * 520;
    const float* w1 = w_s + (1 * 4 + jj) * 520;
    const float* w2 = w_s + (2 * 4 + jj) * 520;
    const float* w3 = w_s + (3 * 4 + jj) * 520;

    for (int t = 0; t < TT; t++) {
        const float* xp = xg + ((size_t)(b * TT + t) << 11) + col;
        float xv0 = __ldcs(xp);
        float xv1 = __ldcs(xp + 512);
        float xv2 = __ldcs(xp + 1024);
        float xv3 = __ldcs(xp + 1536);

        // stage h_prev from L2 (L1 is stale across SMs)
        const float2* ghp = (const float2*)(g_gh[t & 1]);
        for (int v = tid; v < (BB * HH / 2); v += 256) {
            float2 hv = __ldcg(ghp + v);
            int bb = v >> 8;
            int k2 = v & 255;
            *(float2*)(h_s + bb * 514 + k2 * 2) = hv;
        }
        __syncthreads();

        u64 a0 = 0, a1 = 0, a2 = 0, a3 = 0;
        const u64* hb = (const u64*)(h_s + b * 514);
#pragma unroll 16
        for (int kk = 0; kk < 512; kk += 4) {
            u64 h01 = hb[kk >> 1];
            u64 h23 = hb[(kk >> 1) + 1];
            ulonglong2 wv0 = *(const ulonglong2*)(w0 + kk);
            ulonglong2 wv1 = *(const ulonglong2*)(w1 + kk);
            ulonglong2 wv2 = *(const ulonglong2*)(w2 + kk);
            ulonglong2 wv3 = *(const ulonglong2*)(w3 + kk);
            fma2(a0, h01, wv0.x); fma2(a0, h23, wv0.y);
            fma2(a1, h01, wv1.x); fma2(a1, h23, wv1.y);
            fma2(a2, h01, wv2.x); fma2(a2, h23, wv2.y);
            fma2(a3, h01, wv3.x); fma2(a3, h23, wv3.y);
        }
        float2 s0 = upk2(a0), s1 = upk2(a1), s2 = upk2(a2), s3 = upk2(a3);
        float gi = s0.x + s0.y + xv0;
        float gf = s1.x + s1.y + xv1;
        float gg = s2.x + s2.y + xv2;
        float go = s3.x + s3.y + xv3;

        c = sigm(gf) * c + sigm(gi) * tanhf(gg);
        float h = sigm(go) * tanhf(c);

        __stcg(g_gh[(t + 1) & 1] + b * HH + col, h);
        if (hseq)  hseq[((size_t)(b * TT + t) << 9) + col] = h;
        if (hlast && t == TT - 1) hlast[b * HH + col] = h;

        __threadfence();
        __syncthreads();
        if (tid == 0) {
            atomicAdd(&g_bar, 1u);
            unsigned target = gridDim.x * (unsigned)(t + 1);
            volatile unsigned* vb = &g_bar;
            while (*vb < target) { }
        }
        __syncthreads();
    }
}

// ---------------- init: zero ping-pong h and barrier --------------------------
__global__ void init_state() {
    int i = blockIdx.x * blockDim.x + threadIdx.x;
    if (i == 0) g_bar = 0u;
    if (i < 2 * BB * HH) ((float*)g_gh)[i] = 0.0f;
}

// ---------------- final projection [64,512] x [32,512]^T + b ------------------
__global__ void out_gemm(float* __restrict__ out, const float* __restrict__ hl,
                         const float* __restrict__ Wo, const float* __restrict__ bo)
{
    int i = blockIdx.x * blockDim.x + threadIdx.x;
    if (i >= BB * DOUT) return;
    int b = i >> 5, n = i & 31;
    const float4* hp = (const float4*)(hl + b * HH);
    const float4* wp = (const float4*)(Wo + n * HH);
    float s = 0.0f;
#pragma unroll 8
    for (int k = 0; k < HH / 4; k++) {
        float4 hv = hp[k], wv = wp[k];
        s += hv.x * wv.x + hv.y * wv.y + hv.z * wv.z + hv.w * wv.w;
    }
    out[i] = s + bo[n];
}

// ---------------- launch ------------------------------------------------------
extern "C" void kernel_launch(void* const* d_in, const int* in_sizes, int n_in,
                              void* d_out, int out_size)
{
    const float* x    = (const float*)d_in[0];
    const float* Wih0 = (const float*)d_in[1];
    const float* Whh0 = (const float*)d_in[2];
    const float* bih0 = (const float*)d_in[3];
    const float* bhh0 = (const float*)d_in[4];
    const float* Wih1 = (const float*)d_in[5];
    const float* Whh1 = (const float*)d_in[6];
    const float* bih1 = (const float*)d_in[7];
    const float* bhh1 = (const float*)d_in[8];
    const float* Wout = (const float*)d_in[9];
    const float* bout = (const float*)d_in[10];
    float* out = (float*)d_out;

    cudaFuncSetAttribute(lstm_rec, cudaFuncAttributeMaxDynamicSharedMemorySize,
                         SMEM_REC_BYTES);

    void *pxg, *ph1, *phl;
    cudaGetSymbolAddress(&pxg, g_xg);
    cudaGetSymbolAddress(&ph1, g_h1);
    cudaGetSymbolAddress(&phl, g_hlast);
    float* xg = (float*)pxg;
    float* h1 = (float*)ph1;
    float* hl = (float*)phl;

    dim3 ggrid(G4 / 64, (BB * TT) / 64);

    // layer 0
    init_state<<<256, 256>>>();
    gemm_abT<<<ggrid, 256>>>(xg, x, Wih0, bih0, bhh0, BB * TT, G4, DIN);
    lstm_rec<<<128, 256, SMEM_REC_BYTES>>>(Whh0, xg, h1, nullptr);

    // layer 1
    init_state<<<256, 256>>>();
    gemm_abT<<<ggrid, 256>>>(xg, h1, Wih1, bih1, bhh1, BB * TT, G4, HH);
    lstm_rec<<<128, 256, SMEM_REC_BYTES>>>(Whh1, xg, nullptr, hl);

    // output projection
    out_gemm<<<(BB * DOUT + 127) / 128, 128>>>(out, hl, Wout, bout);
}